// round 3
// baseline (speedup 1.0000x reference)
#include <cuda_runtime.h>
#include <math.h>
#include <stdint.h>

#define B   16
#define C   128
#define HH  128
#define WW  128
#define HW  (HH*WW)
#define KK  9
#define KCH 32

// Scratch (no g_mid anymore — dwconv is fused into the GEMM)
__device__ float g_kern[B*C*KK];          // per-(b,c) 3x3 kernels
__device__ float g_att[B*C];              // CA attention
__device__ float g_t[B*C];                // hidden MLP activations

__device__ __forceinline__ float lrelu(float v) { return v > 0.f ? v : 0.1f*v; }

__device__ __forceinline__ float to_tf32(float x) {
    uint32_t u;
    asm("cvt.rna.tf32.f32 %0, %1;" : "=r"(u) : "f"(x));
    return __uint_as_float(u);
}

__device__ __forceinline__ void mma_tf32(float* d, const uint32_t* a, const uint32_t* bf) {
    asm volatile(
        "mma.sync.aligned.m16n8k8.row.col.f32.tf32.tf32.f32 "
        "{%0,%1,%2,%3}, {%4,%5,%6,%7}, {%8,%9}, {%0,%1,%2,%3};"
        : "+f"(d[0]), "+f"(d[1]), "+f"(d[2]), "+f"(d[3])
        : "r"(a[0]), "r"(a[1]), "r"(a[2]), "r"(a[3]), "r"(bf[0]), "r"(bf[1]));
}

// ---------------------------------------------------------------------------
// P1: per-batch MLP hidden layer + CA attention. grid=B, block=256.
// ---------------------------------------------------------------------------
__global__ void prep1_kernel(const float* __restrict__ deg,
                             const float* __restrict__ w1,
                             const float* __restrict__ caw1,
                             const float* __restrict__ caw2)
{
    const int b   = blockIdx.x;
    const int tid = threadIdx.x;

    __shared__ float sdeg[C];
    __shared__ float sr[16];

    if (tid < C) sdeg[tid] = deg[b*C + tid];
    __syncthreads();

    if (tid < C) {
        float acc = 0.f;
        const float* wrow = w1 + tid*C;
        #pragma unroll 8
        for (int c2 = 0; c2 < C; ++c2) acc += sdeg[c2]*wrow[c2];
        g_t[b*C + tid] = lrelu(acc);
    }
    if (tid >= 128 && tid < 144) {
        int r = tid - 128;
        float acc = 0.f;
        const float* wrow = caw1 + r*C;
        #pragma unroll 8
        for (int c2 = 0; c2 < C; ++c2) acc += sdeg[c2]*wrow[c2];
        sr[r] = lrelu(acc);
    }
    __syncthreads();

    if (tid < C) {
        float acc = 0.f;
        const float* wrow = caw2 + tid*16;
        #pragma unroll
        for (int r = 0; r < 16; ++r) acc += sr[r]*wrow[r];
        g_att[b*C + tid] = 1.f/(1.f + expf(-acc));
    }
}

// ---------------------------------------------------------------------------
// P2: kernel coefficients, one warp per output. outputs = B*C*KK = 18432.
// ---------------------------------------------------------------------------
__global__ void prep2_kernel(const float* __restrict__ w2)
{
    const int wid  = threadIdx.x >> 5;
    const int lane = threadIdx.x & 31;
    const int j    = blockIdx.x*8 + wid;
    const int b    = j / (C*KK);
    const int j2   = j - b*(C*KK);

    const float* trow = g_t + b*C;
    const float* wrow = w2 + (size_t)j2*C;

    float acc = 0.f;
    #pragma unroll
    for (int i = 0; i < 4; ++i) {
        const int idx = lane*4 + i;
        acc += trow[idx]*wrow[idx];
    }
    #pragma unroll
    for (int s = 16; s > 0; s >>= 1) acc += __shfl_xor_sync(0xffffffffu, acc, s);
    if (lane == 0) g_kern[(size_t)b*C*KK + j2] = acc;
}

// ---------------------------------------------------------------------------
// Fused kernel: per block = one (b, image row h).
//   producer: dynamic depthwise 3x3 + lrelu computed straight into sB (tf32)
//   main:     TF32 mma over K=128 in chunks of 32
//   epilogue: bias + x0*att residual
// grid = (HH, B), block = 256.
// ---------------------------------------------------------------------------
__global__ void __launch_bounds__(256, 2)
fused_kernel(const float* __restrict__ convw,
             const float* __restrict__ bias,
             const float* __restrict__ x0,
             float* __restrict__ out)
{
    __shared__ float sA[C*36];        // [o][36]  weights (tf32), 32 k + pad
    __shared__ float sB[KCH*136];     // [k][136] dwconv output (tf32), 128 px + pad

    const int b    = blockIdx.y;
    const int h    = blockIdx.x;      // image row == pixel tile
    const int tid  = threadIdx.x;
    const int wid  = tid >> 5;
    const int lane = tid & 31;
    const int g    = lane >> 2;
    const int tg   = lane & 3;
    const int wm0  = (wid >> 2) * 64;
    const int wn0  = (wid & 3) * 32;

    float d[4][4][4];
    #pragma unroll
    for (int mt = 0; mt < 4; ++mt)
        #pragma unroll
        for (int nt = 0; nt < 4; ++nt)
            #pragma unroll
            for (int r = 0; r < 4; ++r) d[mt][nt][r] = 0.f;

    const float* __restrict__ xb = x0 + (size_t)b*C*HW;
    const bool hm = (h > 0);
    const bool hp = (h < HH-1);

    // dwconv producer mapping: 8 threads per channel, 16 px each
    const int pch = tid >> 3;         // 0..31 (channel within chunk)
    const int ppx = (tid & 7) * 16;   // pixel origin

    for (int kc = 0; kc < C; kc += KCH) {
        // --- A chunk: conv weights W[o, kc..kc+31] -> tf32 smem ---
        #pragma unroll
        for (int i = tid; i < C*KCH/4; i += 256) {
            const int o  = i >> 3;
            const int k4 = (i & 7) * 4;
            float4 v = *(const float4*)(convw + o*C + kc + k4);
            float* s = sA + o*36 + k4;
            s[0] = to_tf32(v.x); s[1] = to_tf32(v.y);
            s[2] = to_tf32(v.z); s[3] = to_tf32(v.w);
        }

        // --- B chunk: fused depthwise conv + lrelu -> tf32 smem ---
        {
            const int gc = kc + pch;
            const float* __restrict__ plane = xb + (size_t)gc*HW;
            const float* __restrict__ rowc  = plane + h*WW;
            const float* __restrict__ rowm  = rowc - WW;
            const float* __restrict__ rowp  = rowc + WW;

            float k[9];
            const float* kr = g_kern + ((size_t)b*C + gc)*KK;
            #pragma unroll
            for (int i = 0; i < 9; ++i) k[i] = kr[i];

            float* __restrict__ sbr = sB + pch*136;

            #pragma unroll
            for (int s = 0; s < 4; ++s) {
                const int w0 = ppx + s*4;
                float a0 = 0.f, a1 = 0.f, a2 = 0.f, a3 = 0.f;

                if (hm) {
                    float4 cv = *(const float4*)(rowm + w0);
                    float vl = (w0 > 0)    ? rowm[w0-1] : 0.f;
                    float vr = (w0 < WW-4) ? rowm[w0+4] : 0.f;
                    a0 += k[0]*vl   + k[1]*cv.x + k[2]*cv.y;
                    a1 += k[0]*cv.x + k[1]*cv.y + k[2]*cv.z;
                    a2 += k[0]*cv.y + k[1]*cv.z + k[2]*cv.w;
                    a3 += k[0]*cv.z + k[1]*cv.w + k[2]*vr;
                }
                {
                    float4 cv = *(const float4*)(rowc + w0);
                    float vl = (w0 > 0)    ? rowc[w0-1] : 0.f;
                    float vr = (w0 < WW-4) ? rowc[w0+4] : 0.f;
                    a0 += k[3]*vl   + k[4]*cv.x + k[5]*cv.y;
                    a1 += k[3]*cv.x + k[4]*cv.y + k[5]*cv.z;
                    a2 += k[3]*cv.y + k[4]*cv.z + k[5]*cv.w;
                    a3 += k[3]*cv.z + k[4]*cv.w + k[5]*vr;
                }
                if (hp) {
                    float4 cv = *(const float4*)(rowp + w0);
                    float vl = (w0 > 0)    ? rowp[w0-1] : 0.f;
                    float vr = (w0 < WW-4) ? rowp[w0+4] : 0.f;
                    a0 += k[6]*vl   + k[7]*cv.x + k[8]*cv.y;
                    a1 += k[6]*cv.x + k[7]*cv.y + k[8]*cv.z;
                    a2 += k[6]*cv.y + k[7]*cv.z + k[8]*cv.w;
                    a3 += k[6]*cv.z + k[7]*cv.w + k[8]*vr;
                }
                sbr[w0+0] = to_tf32(lrelu(a0));
                sbr[w0+1] = to_tf32(lrelu(a1));
                sbr[w0+2] = to_tf32(lrelu(a2));
                sbr[w0+3] = to_tf32(lrelu(a3));
            }
        }
        __syncthreads();

        // --- MMA over this k-chunk ---
        #pragma unroll
        for (int ks = 0; ks < KCH; ks += 8) {
            uint32_t a[4][4];
            #pragma unroll
            for (int mt = 0; mt < 4; ++mt) {
                const int o = wm0 + mt*16;
                a[mt][0] = __float_as_uint(sA[(o+g  )*36 + ks + tg    ]);
                a[mt][1] = __float_as_uint(sA[(o+g+8)*36 + ks + tg    ]);
                a[mt][2] = __float_as_uint(sA[(o+g  )*36 + ks + tg + 4]);
                a[mt][3] = __float_as_uint(sA[(o+g+8)*36 + ks + tg + 4]);
            }
            uint32_t bf[4][2];
            #pragma unroll
            for (int nt = 0; nt < 4; ++nt) {
                const int p = wn0 + nt*8 + g;
                bf[nt][0] = __float_as_uint(sB[(ks + tg    )*136 + p]);
                bf[nt][1] = __float_as_uint(sB[(ks + tg + 4)*136 + p]);
            }
            #pragma unroll
            for (int mt = 0; mt < 4; ++mt)
                #pragma unroll
                for (int nt = 0; nt < 4; ++nt)
                    mma_tf32(d[mt][nt], a[mt], bf[nt]);
        }
        __syncthreads();
    }

    // --- fused epilogue: bias + x0*att residual (x0 rows are L2-hot) ---
    const int pix0 = h * WW;
    #pragma unroll
    for (int mt = 0; mt < 4; ++mt) {
        #pragma unroll
        for (int half = 0; half < 2; ++half) {
            const int o  = wm0 + mt*16 + g + half*8;
            const float bo = bias[o];
            const float at = g_att[b*C + o];
            const float* __restrict__ xrow = x0  + ((size_t)(b*C + o))*HW + pix0;
            float* __restrict__       orow = out + ((size_t)(b*C + o))*HW + pix0;
            #pragma unroll
            for (int nt = 0; nt < 4; ++nt) {
                const int cc = wn0 + nt*8 + 2*tg;
                float2 xv = *(const float2*)(xrow + cc);
                float2 ov;
                ov.x = d[mt][nt][half*2 + 0] + bo + xv.x*at;
                ov.y = d[mt][nt][half*2 + 1] + bo + xv.y*at;
                *(float2*)(orow + cc) = ov;
            }
        }
    }
}

// ---------------------------------------------------------------------------
extern "C" void kernel_launch(void* const* d_in, const int* in_sizes, int n_in,
                              void* d_out, int out_size)
{
    const float* x0    = (const float*)d_in[0];
    const float* deg   = (const float*)d_in[1];
    const float* w1    = (const float*)d_in[2];
    const float* w2    = (const float*)d_in[3];
    const float* convw = (const float*)d_in[4];
    const float* convb = (const float*)d_in[5];
    const float* caw1  = (const float*)d_in[6];
    const float* caw2  = (const float*)d_in[7];
    float* out = (float*)d_out;

    prep1_kernel<<<B, 256>>>(deg, w1, caw1, caw2);
    prep2_kernel<<<(B*C*KK)/8, 256>>>(w2);
    fused_kernel<<<dim3(HH, B), 256>>>(convw, convb, x0, out);
}

// round 4
// speedup vs baseline: 1.6666x; 1.6666x over previous
#include <cuda_runtime.h>
#include <cuda_fp16.h>
#include <math.h>
#include <stdint.h>

#define B    16
#define C    128
#define HH   128
#define WW   128
#define HW   (HH*WW)
#define KK   9
#define KCH  32
#define NCHUNK (C/KCH)

// Scratch
__device__ __half g_midh[(size_t)B*C*HW];  // depthwise output (fp16, 64 MB)
__device__ __half g_wh[C*C];               // conv weights fp16 [o][k]
__device__ float  g_kern[B*C*KK];          // per-(b,c) 3x3 kernels
__device__ float  g_att[B*C];              // CA attention
__device__ float  g_t[B*C];                // hidden MLP activations

__device__ __forceinline__ float lrelu(float v) { return v > 0.f ? v : 0.1f*v; }

__device__ __forceinline__ void cp16(void* dst, const void* src) {
    uint32_t d = (uint32_t)__cvta_generic_to_shared(dst);
    asm volatile("cp.async.cg.shared.global [%0], [%1], 16;" :: "r"(d), "l"(src));
}
__device__ __forceinline__ void cp_commit() {
    asm volatile("cp.async.commit_group;");
}

__device__ __forceinline__ void ldmatrix_x4(uint32_t* r, const void* p) {
    uint32_t a = (uint32_t)__cvta_generic_to_shared(p);
    asm volatile("ldmatrix.sync.aligned.m8n8.x4.shared.b16 {%0,%1,%2,%3}, [%4];"
                 : "=r"(r[0]), "=r"(r[1]), "=r"(r[2]), "=r"(r[3]) : "r"(a));
}
__device__ __forceinline__ void ldmatrix_x2_t(uint32_t* r, const void* p) {
    uint32_t a = (uint32_t)__cvta_generic_to_shared(p);
    asm volatile("ldmatrix.sync.aligned.m8n8.x2.trans.shared.b16 {%0,%1}, [%2];"
                 : "=r"(r[0]), "=r"(r[1]) : "r"(a));
}
__device__ __forceinline__ void mma_f16(float* d, const uint32_t* a, const uint32_t* b) {
    asm volatile(
        "mma.sync.aligned.m16n8k16.row.col.f32.f16.f16.f32 "
        "{%0,%1,%2,%3}, {%4,%5,%6,%7}, {%8,%9}, {%0,%1,%2,%3};"
        : "+f"(d[0]), "+f"(d[1]), "+f"(d[2]), "+f"(d[3])
        : "r"(a[0]), "r"(a[1]), "r"(a[2]), "r"(a[3]), "r"(b[0]), "r"(b[1]));
}

// ---------------------------------------------------------------------------
// P1: per-batch MLP hidden + CA attention (warp-per-output) + fp16 W convert
// grid = B, block = 256 (8 warps). 144 dots of length 128 per batch.
// ---------------------------------------------------------------------------
__global__ void prep1_kernel(const float* __restrict__ deg,
                             const float* __restrict__ w1,
                             const float* __restrict__ caw1,
                             const float* __restrict__ caw2,
                             const float* __restrict__ convw)
{
    const int b    = blockIdx.x;
    const int tid  = threadIdx.x;
    const int wid  = tid >> 5;
    const int lane = tid & 31;

    __shared__ float sdeg[C];
    __shared__ float sr[16];

    if (tid < C) sdeg[tid] = deg[b*C + tid];
    __syncthreads();

    // 144 dot products: j = wid + 8*i ; j<128 -> t_j, j>=128 -> CA hidden
    #pragma unroll
    for (int i = 0; i < 18; ++i) {
        const int j = wid + 8*i;
        const float* wrow = (j < 128) ? (w1 + j*C) : (caw1 + (j-128)*C);
        float acc = 0.f;
        #pragma unroll
        for (int u = 0; u < 4; ++u) {
            const int idx = lane*4 + u;
            acc += sdeg[idx]*wrow[idx];
        }
        #pragma unroll
        for (int s = 16; s > 0; s >>= 1) acc += __shfl_xor_sync(0xffffffffu, acc, s);
        if (lane == 0) {
            if (j < 128) g_t[b*C + j] = lrelu(acc);
            else         sr[j-128]    = lrelu(acc);
        }
    }
    __syncthreads();

    if (tid < C) {
        float acc = 0.f;
        const float* wrow = caw2 + tid*16;
        #pragma unroll
        for (int r = 0; r < 16; ++r) acc += sr[r]*wrow[r];
        g_att[b*C + tid] = 1.f/(1.f + expf(-acc));
    }

    // fp32 -> fp16 weight conversion, 1024 elems per block
    {
        const int base = b*1024 + tid*4;
        float4 v = *(const float4*)(convw + base);
        g_wh[base+0] = __float2half(v.x);
        g_wh[base+1] = __float2half(v.y);
        g_wh[base+2] = __float2half(v.z);
        g_wh[base+3] = __float2half(v.w);
    }
}

// ---------------------------------------------------------------------------
// P2: kernel coefficients, one warp per output (B*C*KK = 18432 dots of 128)
// ---------------------------------------------------------------------------
__global__ void prep2_kernel(const float* __restrict__ w2)
{
    const int wid  = threadIdx.x >> 5;
    const int lane = threadIdx.x & 31;
    const int j    = blockIdx.x*8 + wid;
    const int b    = j / (C*KK);
    const int j2   = j - b*(C*KK);

    const float* trow = g_t + b*C;
    const float* wrow = w2 + (size_t)j2*C;

    float acc = 0.f;
    #pragma unroll
    for (int i = 0; i < 4; ++i) {
        const int idx = lane*4 + i;
        acc += trow[idx]*wrow[idx];
    }
    #pragma unroll
    for (int s = 16; s > 0; s >>= 1) acc += __shfl_xor_sync(0xffffffffu, acc, s);
    if (lane == 0) g_kern[(size_t)b*C*KK + j2] = acc;
}

// ---------------------------------------------------------------------------
// dwconv: per-(b,c) dynamic 3x3 depthwise + lrelu, fp16 output.
// grid = B*C, block = 256, 4 px/thread.
// ---------------------------------------------------------------------------
__global__ void dwconv_kernel(const float* __restrict__ x0)
{
    const int bc = blockIdx.x;
    const float* __restrict__ src = x0 + (size_t)bc*HW;
    __half* __restrict__ dst = g_midh + (size_t)bc*HW;

    float k[9];
    #pragma unroll
    for (int i = 0; i < 9; ++i) k[i] = g_kern[bc*9 + i];

    for (int p4 = threadIdx.x*4; p4 < HW; p4 += blockDim.x*4) {
        const int h  = p4 >> 7;
        const int w0 = p4 & (WW-1);
        float a0 = 0.f, a1 = 0.f, a2 = 0.f, a3 = 0.f;

        #pragma unroll
        for (int kh = 0; kh < 3; ++kh) {
            const int hh = h + kh - 1;
            if (hh < 0 || hh >= HH) continue;
            const float* row = src + hh*WW;
            float4 cv = *(const float4*)(row + w0);
            float vl = (w0 > 0)    ? row[w0-1] : 0.f;
            float vr = (w0 < WW-4) ? row[w0+4] : 0.f;
            const float k0 = k[kh*3+0], k1 = k[kh*3+1], k2 = k[kh*3+2];
            a0 += k0*vl   + k1*cv.x + k2*cv.y;
            a1 += k0*cv.x + k1*cv.y + k2*cv.z;
            a2 += k0*cv.y + k1*cv.z + k2*cv.w;
            a3 += k0*cv.z + k1*cv.w + k2*vr;
        }
        __half2 h01 = __floats2half2_rn(lrelu(a0), lrelu(a1));
        __half2 h23 = __floats2half2_rn(lrelu(a2), lrelu(a3));
        uint2 pk;
        pk.x = *(uint32_t*)&h01;
        pk.y = *(uint32_t*)&h23;
        *(uint2*)(dst + p4) = pk;
    }
}

// ---------------------------------------------------------------------------
// GEMM (fp16 mma m16n8k16, cp.async double-buffered) + fused epilogue
// out[b,o,p] = sum_k W[o,k]*mid[b,k,p] + bias[o] + x0[b,o,p]*att[b,o]
// Block = one (b, image row h): M=128(o), N=128(p=w), K=128 in 4 chunks of 32.
// grid = (HH, B), block = 256 (8 warps, each 64x32).
// ---------------------------------------------------------------------------
#define SA_STRIDE 40    // halves: 32 data + 8 pad  (80 B rows, conflict-free)
#define SB_STRIDE 136   // halves: 128 data + 8 pad (272 B rows, conflict-free)

__global__ void __launch_bounds__(256, 2)
gemm_f16(const float* __restrict__ bias,
         const float* __restrict__ x0,
         float* __restrict__ out)
{
    __shared__ __align__(16) __half sA[2][C*SA_STRIDE];    // [o][k-chunk]
    __shared__ __align__(16) __half sB[2][KCH*SB_STRIDE];  // [k][p]

    const int b    = blockIdx.y;
    const int h    = blockIdx.x;
    const int tid  = threadIdx.x;
    const int wid  = tid >> 5;
    const int lane = tid & 31;
    const int g    = lane >> 2;
    const int tg   = lane & 3;
    const int wm0  = (wid >> 2) * 64;
    const int wn0  = (wid & 3) * 32;

    float d[4][4][4];
    #pragma unroll
    for (int mt = 0; mt < 4; ++mt)
        #pragma unroll
        for (int nt = 0; nt < 4; ++nt)
            #pragma unroll
            for (int r = 0; r < 4; ++r) d[mt][nt][r] = 0.f;

    const __half* __restrict__ midb = g_midh + ((size_t)b*C)*HW + h*WW;

    // cp.async chunk loader: 2 sB segs + 2 sA segs per thread
    const int sbk = tid >> 3;            // 0..31 (k row)
    const int sbs = (tid & 7) * 2;       // seg pair within row (16 segs of 16B)
    const int sao = tid >> 1;            // 0..127 (o row)
    const int sas = (tid & 1) * 2;       // seg pair within row (4 segs of 16B)

#define LOAD_CHUNK(cc, buf) do {                                               \
        const __half* srcB = midb + (size_t)((cc)*KCH + sbk)*HW + sbs*8;       \
        __half* dstB = &sB[buf][sbk*SB_STRIDE + sbs*8];                        \
        cp16(dstB,     srcB);                                                  \
        cp16(dstB + 8, srcB + 8);                                              \
        const __half* srcA = g_wh + sao*C + (cc)*KCH + sas*8;                  \
        __half* dstA = &sA[buf][sao*SA_STRIDE + sas*8];                        \
        cp16(dstA,     srcA);                                                  \
        cp16(dstA + 8, srcA + 8);                                              \
        cp_commit();                                                           \
    } while (0)

    LOAD_CHUNK(0, 0);

    #pragma unroll
    for (int c = 0; c < NCHUNK; ++c) {
        const int buf = c & 1;
        if (c + 1 < NCHUNK) {
            LOAD_CHUNK(c + 1, (c + 1) & 1);
            asm volatile("cp.async.wait_group 1;");
        } else {
            asm volatile("cp.async.wait_group 0;");
        }
        __syncthreads();

        #pragma unroll
        for (int ks = 0; ks < KCH; ks += 16) {
            uint32_t af[4][4];
            const int arow = lane & 15;
            const int acol = ks + ((lane >> 4) << 3);
            #pragma unroll
            for (int mt = 0; mt < 4; ++mt)
                ldmatrix_x4(af[mt], &sA[buf][(wm0 + mt*16 + arow)*SA_STRIDE + acol]);

            uint32_t bf[4][2];
            const int brow = ks + (lane & 15);
            #pragma unroll
            for (int nt = 0; nt < 4; ++nt)
                ldmatrix_x2_t(bf[nt], &sB[buf][brow*SB_STRIDE + wn0 + nt*8]);

            #pragma unroll
            for (int mt = 0; mt < 4; ++mt)
                #pragma unroll
                for (int nt = 0; nt < 4; ++nt)
                    mma_f16(d[mt][nt], af[mt], bf[nt]);
        }
        __syncthreads();
    }

    // --- fused epilogue: bias + x0*att residual ---
    const int pix0 = h * WW;
    #pragma unroll
    for (int mt = 0; mt < 4; ++mt) {
        #pragma unroll
        for (int half = 0; half < 2; ++half) {
            const int o  = wm0 + mt*16 + g + half*8;
            const float bo = bias[o];
            const float at = g_att[b*C + o];
            const float* __restrict__ xrow = x0  + ((size_t)(b*C + o))*HW + pix0;
            float* __restrict__       orow = out + ((size_t)(b*C + o))*HW + pix0;
            #pragma unroll
            for (int nt = 0; nt < 4; ++nt) {
                const int cc = wn0 + nt*8 + 2*tg;
                float2 xv = *(const float2*)(xrow + cc);
                float2 ov;
                ov.x = d[mt][nt][half*2 + 0] + bo + xv.x*at;
                ov.y = d[mt][nt][half*2 + 1] + bo + xv.y*at;
                *(float2*)(orow + cc) = ov;
            }
        }
    }
}

// ---------------------------------------------------------------------------
extern "C" void kernel_launch(void* const* d_in, const int* in_sizes, int n_in,
                              void* d_out, int out_size)
{
    const float* x0    = (const float*)d_in[0];
    const float* deg   = (const float*)d_in[1];
    const float* w1    = (const float*)d_in[2];
    const float* w2    = (const float*)d_in[3];
    const float* convw = (const float*)d_in[4];
    const float* convb = (const float*)d_in[5];
    const float* caw1  = (const float*)d_in[6];
    const float* caw2  = (const float*)d_in[7];
    float* out = (float*)d_out;

    prep1_kernel<<<B, 256>>>(deg, w1, caw1, caw2, convw);
    prep2_kernel<<<(B*C*KK)/8, 256>>>(w2);
    dwconv_kernel<<<B*C, 256>>>(x0);
    gemm_f16<<<dim3(HH, B), 256>>>(convb, x0, out);
}